// round 3
// baseline (speedup 1.0000x reference)
#include <cuda_runtime.h>
#include <cstdint>

// Shapes (fixed by the problem)
#define B 8
#define N 256
#define IN 64
#define F 64          // H*D
#define H 8
#define D 8
#define RPC 4         // rows (i values) per CTA in the attention kernel
#define QROWS 16      // rows per CTA in the qkv kernel

#define L2E 1.4426950408889634f

// Scratch (allocation-free rule: __device__ globals)
__device__ float g_Q[B * N * F];
__device__ float g_K[B * N * F];   // pre-scaled by D^-0.5
__device__ float g_V[B * N * F];

// ---------------------------------------------------------------------------
// Kernel A: Q/K/V projections. grid = B*N/QROWS = 128 blocks, 256 threads.
// Thread owns one f-column and 4 rows (stride 4). W cached via L1.
// ---------------------------------------------------------------------------
__global__ void __launch_bounds__(256) qkv_kernel(
    const float* __restrict__ h,
    const float* __restrict__ Wq,
    const float* __restrict__ Wk,
    const float* __restrict__ Wv)
{
    __shared__ float hs[QROWS][IN];   // 4 KB

    const int tid = threadIdx.x;
    const int f   = tid & 63;
    const int rq  = tid >> 6;         // 0..3
    const int row0 = blockIdx.x * QROWS;

    for (int t = tid; t < QROWS * IN; t += 256)
        ((float*)hs)[t] = h[row0 * IN + t];
    __syncthreads();

    float aq[4] = {0, 0, 0, 0}, ak[4] = {0, 0, 0, 0}, av[4] = {0, 0, 0, 0};
#pragma unroll 8
    for (int k = 0; k < IN; k++) {
        float wq = Wq[k * F + f];
        float wk = Wk[k * F + f];
        float wv = Wv[k * F + f];
#pragma unroll
        for (int rr = 0; rr < 4; rr++) {
            float hv = hs[rq + 4 * rr][k];
            aq[rr] = fmaf(hv, wq, aq[rr]);
            ak[rr] = fmaf(hv, wk, ak[rr]);
            av[rr] = fmaf(hv, wv, av[rr]);
        }
    }
#pragma unroll
    for (int rr = 0; rr < 4; rr++) {
        int row = row0 + rq + 4 * rr;
        g_Q[row * F + f] = aq[rr];
        g_K[row * F + f] = ak[rr] * 0.35355339059327373f;  // D^-0.5
        g_V[row * F + f] = av[rr];
    }
}

// ---------------------------------------------------------------------------
// Kernel B: fused qk + softmax(fixed-shift) + weighted sum.
// grid = B*(N/RPC) = 512 blocks, 256 threads (8 warps).
// Warp pair (2w, 2w+1) shares row r=w, splitting j in halves of 128.
// ---------------------------------------------------------------------------
__global__ void __launch_bounds__(256, 3) attn_kernel(
    const float* __restrict__ e_att,
    const float* __restrict__ e_value,
    const uint32_t* __restrict__ attn_mask,   // 4-byte elems; true <=> nonzero
    float* __restrict__ out)
{
    __shared__ float qk_s[RPC][N][H];    // 32 KB; holds qk*log2e - M2 after transform
    __shared__ float q_s[RPC][F];        // 1 KB
    __shared__ float msk_s[RPC][N];      // 4 KB
    __shared__ float part[8][32][4];     // 4 KB partial (l0,l1,a0,a1)

    const int blk  = blockIdx.x;
    const int b    = blk >> 6;           // 64 blocks per batch
    const int i0   = (blk & 63) * RPC;
    const int tid  = threadIdx.x;
    const int wid  = tid >> 5;           // 0..7
    const int lane = tid & 31;

    // ---- load Q rows + mask into smem ----
    for (int t = tid; t < RPC * F; t += 256) {
        int r = t >> 6, f = t & 63;
        q_s[r][f] = g_Q[(b * N + i0 + r) * F + f];
    }
    for (int t = tid; t < RPC * N; t += 256) {
        int r = t >> 8, j = t & 255;
        msk_s[r][j] = (attn_mask[(b * N + i0 + r) * N + j] != 0u) ? 1.0f : 0.0f;
    }
    __syncthreads();

    // ---- phase 1: qk[r][j][h] = dot8(Q[r,h,:], K[b,j,h,:]); warp owns 32 j's ----
    {
        const int h  = lane >> 2;        // 0..7
        const int jm = lane & 3;         // 0..3
        float qreg[RPC][8];
#pragma unroll
        for (int r = 0; r < RPC; r++)
#pragma unroll
            for (int d = 0; d < 8; d++)
                qreg[r][d] = q_s[r][h * 8 + d];

        const float4* Kb = (const float4*)(g_K + b * N * F);
        for (int jg = wid * 8; jg < wid * 8 + 8; jg++) {
            int j = jm + 4 * jg;
            float4 k0 = Kb[j * 16 + h * 2];
            float4 k1 = Kb[j * 16 + h * 2 + 1];
#pragma unroll
            for (int r = 0; r < RPC; r++) {
                float s = qreg[r][0] * k0.x;
                s = fmaf(qreg[r][1], k0.y, s);
                s = fmaf(qreg[r][2], k0.z, s);
                s = fmaf(qreg[r][3], k0.w, s);
                s = fmaf(qreg[r][4], k1.x, s);
                s = fmaf(qreg[r][5], k1.y, s);
                s = fmaf(qreg[r][6], k1.z, s);
                s = fmaf(qreg[r][7], k1.w, s);
                qk_s[r][j][h] = s;
            }
        }
    }
    __syncthreads();

    // ---- phase 2: per-row shift; transform qk' = qk*L2E - (max+10)*L2E ----
    if (wid < 4) {
        const int r = wid;
        float* qf = &qk_s[r][0][0];
        float mx = -1e30f;
        for (int t = lane; t < N * H; t += 32) mx = fmaxf(mx, qf[t]);
#pragma unroll
        for (int o = 16; o; o >>= 1) mx = fmaxf(mx, __shfl_xor_sync(0xffffffffu, mx, o));
        float M2 = (mx + 10.0f) * L2E;
        for (int t = lane; t < N * H; t += 32)
            qf[t] = fmaf(qf[t], L2E, -M2);
    }
    __syncthreads();

    // ---- phase 3: streaming softmax + weighted accumulation (half j-range) ----
    {
        const int r     = wid >> 1;
        const int jhalf = wid & 1;
        const int i     = i0 + r;
        const int h     = lane >> 2;
        const int j0    = jhalf * 128;

        const float2* ea = (const float2*)(e_att   + (size_t)(b * N + i) * N * F) + lane + j0 * 32;
        const float2* ev = (const float2*)(e_value + (size_t)(b * N + i) * N * F) + lane + j0 * 32;
        const float2* Vb = (const float2*)(g_V + b * N * F) + lane;

        float l0 = 0.f, l1 = 0.f, a0 = 0.f, a1 = 0.f;

#pragma unroll 2
        for (int jj = 0; jj < 128; jj += 2) {
            // batch all six loads before the dependent math
            float2 ea0 = ea[jj * 32];
            float2 ea1 = ea[jj * 32 + 32];
            float2 ev0 = ev[jj * 32];
            float2 ev1 = ev[jj * 32 + 32];
            float2 v0  = Vb[(j0 + jj) * 32];
            float2 v1  = Vb[(j0 + jj + 1) * 32];

            float qk0 = qk_s[r][j0 + jj][h];
            float qk1 = qk_s[r][j0 + jj + 1][h];
            float m0  = msk_s[r][j0 + jj];
            float m1  = msk_s[r][j0 + jj + 1];

            float p00 = exp2f(fmaf(ea0.x, L2E, qk0)) * m0;
            float p01 = exp2f(fmaf(ea0.y, L2E, qk0)) * m0;
            float p10 = exp2f(fmaf(ea1.x, L2E, qk1)) * m1;
            float p11 = exp2f(fmaf(ea1.y, L2E, qk1)) * m1;

            l0 += p00 + p10;
            l1 += p01 + p11;
            a0 = fmaf(p00, v0.x + ev0.x, a0);
            a1 = fmaf(p01, v0.y + ev0.y, a1);
            a0 = fmaf(p10, v1.x + ev1.x, a0);
            a1 = fmaf(p11, v1.y + ev1.y, a1);
        }

        part[wid][lane][0] = l0;
        part[wid][lane][1] = l1;
        part[wid][lane][2] = a0;
        part[wid][lane][3] = a1;
    }
    __syncthreads();

    // ---- combine halves + write out (warps 0..3, row = wid) ----
    if (wid < 4) {
        const int r = wid;
        const int i = i0 + r;
        float L0 = part[2 * r][lane][0] + part[2 * r + 1][lane][0];
        float L1 = part[2 * r][lane][1] + part[2 * r + 1][lane][1];
        float A0 = part[2 * r][lane][2] + part[2 * r + 1][lane][2];
        float A1 = part[2 * r][lane][3] + part[2 * r + 1][lane][3];
        float2 o;
        o.x = (L0 > 0.f) ? A0 / L0 : 0.f;
        o.y = (L1 > 0.f) ? A1 / L1 : 0.f;
        ((float2*)(out + (size_t)(b * N + i) * F))[lane] = o;
    }
}

// ---------------------------------------------------------------------------
extern "C" void kernel_launch(void* const* d_in, const int* in_sizes, int n_in,
                              void* d_out, int out_size)
{
    const float*    h       = (const float*)d_in[0];
    const float*    e_att   = (const float*)d_in[1];
    const float*    e_value = (const float*)d_in[2];
    const uint32_t* mask    = (const uint32_t*)d_in[3];
    const float*    Wq      = (const float*)d_in[4];
    const float*    Wk      = (const float*)d_in[5];
    const float*    Wv      = (const float*)d_in[6];
    float*          out     = (float*)d_out;

    qkv_kernel<<<(B * N) / QROWS, 256>>>(h, Wq, Wk, Wv);
    attn_kernel<<<B * (N / RPC), 256>>>(e_att, e_value, mask, out);
}

// round 4
// speedup vs baseline: 1.1636x; 1.1636x over previous
#include <cuda_runtime.h>
#include <cstdint>

// Shapes (fixed by the problem)
#define B 8
#define N 256
#define IN 64
#define F 64          // H*D
#define H 8
#define D 8
#define RPC 4         // rows (i values) per CTA in the attention kernel
#define QROWS 8       // rows per CTA in the qkv kernel

#define L2E 1.4426950408889634f

// Scratch (allocation-free rule: __device__ globals)
__device__ float g_Q[B * N * F];
__device__ float g_K[B * N * F];   // pre-scaled by D^-0.5
__device__ float g_V[B * N * F];

// ---------------------------------------------------------------------------
// Kernel A: Q/K/V projections. grid = B*N/QROWS = 256 blocks, 256 threads.
// Thread owns one f-column and 2 rows. W cached via L1/L2.
// ---------------------------------------------------------------------------
__global__ void __launch_bounds__(256) qkv_kernel(
    const float* __restrict__ h,
    const float* __restrict__ Wq,
    const float* __restrict__ Wk,
    const float* __restrict__ Wv)
{
    __shared__ float hs[QROWS][IN];   // 2 KB

    const int tid  = threadIdx.x;
    const int f    = tid & 63;
    const int rq   = tid >> 6;        // 0..3
    const int row0 = blockIdx.x * QROWS;

    for (int t = tid; t < QROWS * IN; t += 256)
        ((float*)hs)[t] = h[row0 * IN + t];
    __syncthreads();

    float aq[2] = {0, 0}, ak[2] = {0, 0}, av[2] = {0, 0};
#pragma unroll 8
    for (int k = 0; k < IN; k++) {
        float wq = Wq[k * F + f];
        float wk = Wk[k * F + f];
        float wv = Wv[k * F + f];
#pragma unroll
        for (int rr = 0; rr < 2; rr++) {
            float hv = hs[rq + 4 * rr][k];
            aq[rr] = fmaf(hv, wq, aq[rr]);
            ak[rr] = fmaf(hv, wk, ak[rr]);
            av[rr] = fmaf(hv, wv, av[rr]);
        }
    }
#pragma unroll
    for (int rr = 0; rr < 2; rr++) {
        int row = row0 + rq + 4 * rr;
        g_Q[row * F + f] = aq[rr];
        g_K[row * F + f] = ak[rr] * 0.35355339059327373f;  // D^-0.5
        g_V[row * F + f] = av[rr];
    }
}

// ---------------------------------------------------------------------------
// Kernel B: fused qk + softmax(fixed-shift) + weighted sum.
// grid = B*(N/RPC) = 512 blocks, 256 threads (8 warps), 4 CTAs/SM.
// Warp pair (2w, 2w+1) shares row r=w, splitting j into halves of 128.
// Within a warp: lanes 0-15 handle j-row (jo=0), lanes 16-31 handle j+1 (jo=1);
// lane's q = lane&15 owns floats [4q, 4q+4) of the 64-wide f dimension (float4).
// ---------------------------------------------------------------------------
__global__ void __launch_bounds__(256, 4) attn_kernel(
    const float* __restrict__ e_att,
    const float* __restrict__ e_value,
    const uint32_t* __restrict__ attn_mask,   // 4-byte elems; true <=> nonzero
    float* __restrict__ out)
{
    __shared__ float qk_s[RPC][N][H];    // 32 KB; holds qk*log2e - M2 after transform
    __shared__ float q_s[RPC][F];        // 1 KB
    __shared__ float msk_s[RPC][N];      // 4 KB
    __shared__ float part[8][32][8];     // 8 KB: per (wid,lane): l0..3, a0..3

    const int blk  = blockIdx.x;
    const int b    = blk >> 6;           // 64 blocks per batch
    const int i0   = (blk & 63) * RPC;
    const int tid  = threadIdx.x;
    const int wid  = tid >> 5;           // 0..7
    const int lane = tid & 31;

    // ---- load Q rows + mask into smem ----
    for (int t = tid; t < RPC * F; t += 256) {
        int r = t >> 6, f = t & 63;
        q_s[r][f] = g_Q[(b * N + i0 + r) * F + f];
    }
    for (int t = tid; t < RPC * N; t += 256) {
        int r = t >> 8, j = t & 255;
        msk_s[r][j] = (attn_mask[(b * N + i0 + r) * N + j] != 0u) ? 1.0f : 0.0f;
    }
    __syncthreads();

    // ---- phase 1: qk[r][j][h] = dot8(Q[r,h,:], K[b,j,h,:]); warp owns 32 j's ----
    {
        const int h  = lane >> 2;        // 0..7
        const int jm = lane & 3;         // 0..3
        float qreg[RPC][8];
#pragma unroll
        for (int r = 0; r < RPC; r++)
#pragma unroll
            for (int d = 0; d < 8; d++)
                qreg[r][d] = q_s[r][h * 8 + d];

        const float4* Kb = (const float4*)(g_K + b * N * F);
        for (int jg = wid * 8; jg < wid * 8 + 8; jg++) {
            int j = jm + 4 * jg;
            float4 k0 = Kb[j * 16 + h * 2];
            float4 k1 = Kb[j * 16 + h * 2 + 1];
#pragma unroll
            for (int r = 0; r < RPC; r++) {
                float s = qreg[r][0] * k0.x;
                s = fmaf(qreg[r][1], k0.y, s);
                s = fmaf(qreg[r][2], k0.z, s);
                s = fmaf(qreg[r][3], k0.w, s);
                s = fmaf(qreg[r][4], k1.x, s);
                s = fmaf(qreg[r][5], k1.y, s);
                s = fmaf(qreg[r][6], k1.z, s);
                s = fmaf(qreg[r][7], k1.w, s);
                qk_s[r][j][h] = s;
            }
        }
    }
    __syncthreads();

    // ---- phase 2: per-row shift; transform qk' = qk*L2E - (max+10)*L2E ----
    if (wid < 4) {
        const int r = wid;
        float* qf = &qk_s[r][0][0];
        float mx = -1e30f;
        for (int t = lane; t < N * H; t += 32) mx = fmaxf(mx, qf[t]);
#pragma unroll
        for (int o = 16; o; o >>= 1) mx = fmaxf(mx, __shfl_xor_sync(0xffffffffu, mx, o));
        float M2 = (mx + 10.0f) * L2E;
        for (int t = lane; t < N * H; t += 32)
            qf[t] = fmaf(qf[t], L2E, -M2);
    }
    __syncthreads();

    // ---- phase 3: streaming softmax + weighted accumulation ----
    {
        const int r     = wid >> 1;
        const int jhalf = wid & 1;
        const int i     = i0 + r;
        const int jo    = lane >> 4;     // 0/1: which of the 2 j's per step
        const int q     = lane & 15;     // float4 index in the f dim
        const int h     = q >> 1;
        const int j0    = jhalf * 128;

        const float4* pea = (const float4*)(e_att   + (size_t)(b * N + i) * N * F);
        const float4* pev = (const float4*)(e_value + (size_t)(b * N + i) * N * F);
        const float4* pV  = (const float4*)(g_V + b * N * F);

        float l0 = 0.f, l1 = 0.f, l2 = 0.f, l3 = 0.f;
        float a0 = 0.f, a1 = 0.f, a2 = 0.f, a3 = 0.f;

        int idx = (j0 + jo) * 16 + q;
        float4 EA = pea[idx];
        float4 EV = pev[idx];
        float4 VV = pV[idx];

#pragma unroll 2
        for (int jj = 0; jj < 128; jj += 2) {
            // prefetch next step (clamped so last iteration re-loads safely)
            int idxn = (jj < 126) ? idx + 32 : idx;
            float4 nEA = pea[idxn];
            float4 nEV = pev[idxn];
            float4 nVV = pV[idxn];

            int   j  = j0 + jj + jo;
            float qk = qk_s[r][j][h];
            float mf = msk_s[r][j];

            float p0 = exp2f(fmaf(EA.x, L2E, qk)) * mf;
            float p1 = exp2f(fmaf(EA.y, L2E, qk)) * mf;
            float p2 = exp2f(fmaf(EA.z, L2E, qk)) * mf;
            float p3 = exp2f(fmaf(EA.w, L2E, qk)) * mf;

            l0 += p0; l1 += p1; l2 += p2; l3 += p3;
            a0 = fmaf(p0, VV.x + EV.x, a0);
            a1 = fmaf(p1, VV.y + EV.y, a1);
            a2 = fmaf(p2, VV.z + EV.z, a2);
            a3 = fmaf(p3, VV.w + EV.w, a3);

            EA = nEA; EV = nEV; VV = nVV;
            idx = idxn;
        }

        part[wid][lane][0] = l0;
        part[wid][lane][1] = l1;
        part[wid][lane][2] = l2;
        part[wid][lane][3] = l3;
        part[wid][lane][4] = a0;
        part[wid][lane][5] = a1;
        part[wid][lane][6] = a2;
        part[wid][lane][7] = a3;
    }
    __syncthreads();

    // ---- combine 4 partials per (r, f4) and write out ----
    if (wid < 4 && lane < 16) {
        const int r = wid;
        const int i = i0 + r;
        const int q = lane;
        float L[4], A[4];
#pragma unroll
        for (int c = 0; c < 4; c++) {
            L[c] = part[2 * r][q][c]      + part[2 * r][16 + q][c]
                 + part[2 * r + 1][q][c]  + part[2 * r + 1][16 + q][c];
            A[c] = part[2 * r][q][4 + c]     + part[2 * r][16 + q][4 + c]
                 + part[2 * r + 1][q][4 + c] + part[2 * r + 1][16 + q][4 + c];
        }
        float4 o;
        o.x = (L[0] > 0.f) ? A[0] / L[0] : 0.f;
        o.y = (L[1] > 0.f) ? A[1] / L[1] : 0.f;
        o.z = (L[2] > 0.f) ? A[2] / L[2] : 0.f;
        o.w = (L[3] > 0.f) ? A[3] / L[3] : 0.f;
        ((float4*)(out + (size_t)(b * N + i) * F))[q] = o;
    }
}

// ---------------------------------------------------------------------------
extern "C" void kernel_launch(void* const* d_in, const int* in_sizes, int n_in,
                              void* d_out, int out_size)
{
    const float*    h       = (const float*)d_in[0];
    const float*    e_att   = (const float*)d_in[1];
    const float*    e_value = (const float*)d_in[2];
    const uint32_t* mask    = (const uint32_t*)d_in[3];
    const float*    Wq      = (const float*)d_in[4];
    const float*    Wk      = (const float*)d_in[5];
    const float*    Wv      = (const float*)d_in[6];
    float*          out     = (float*)d_out;

    qkv_kernel<<<(B * N) / QROWS, 256>>>(h, Wq, Wk, Wv);
    attn_kernel<<<B * (N / RPC), 256>>>(e_att, e_value, mask, out);
}